// round 15
// baseline (speedup 1.0000x reference)
#include <cuda_runtime.h>

#define T_LEN 2048
#define BATCH 32
#define HID   128
#define DIN   256
#define HPAD  (HID + 4)   // +4-float skew: the two 64-unit halves hit
                          // disjoint bank groups (256B->same banks; 272B->+4)

typedef unsigned long long ull;

// Scratch: input projection [T][B][H], layer-0 hidden stream [B][T][H], flags.
__device__ float g_xp[(size_t)T_LEN * BATCH * HID];
__device__ float g_h0[(size_t)BATCH * T_LEN * HID];
__device__ int   g_flag[BATCH * T_LEN];

__device__ __forceinline__ void fma2(ull& acc, ull w, ull h) {
    asm("fma.rn.f32x2 %0, %1, %2, %0;" : "+l"(acc) : "l"(w), "l"(h));
}
__device__ __forceinline__ float sum2(ull a) {
    float lo, hi;
    asm("mov.b64 {%0, %1}, %2;" : "=f"(lo), "=f"(hi) : "l"(a));
    return lo + hi;
}
__device__ __forceinline__ ull dup2(float f) {
    ull r;
    asm("mov.b64 %0, {%1, %1};" : "=l"(r) : "f"(f));
    return r;
}
__device__ __forceinline__ void unpack2(ull a, float& lo, float& hi) {
    asm("mov.b64 {%0, %1}, %2;" : "=f"(lo), "=f"(hi) : "l"(a));
}
__device__ __forceinline__ int ldacq(const int* p) {
    int v;
    asm volatile("ld.acquire.gpu.global.b32 %0, [%1];" : "=r"(v) : "l"(p));
    return v;
}
// Release store: orders all prior stores (including other threads' stores
// ordered-before via the preceding __syncthreads, by PTX-model cumulativity)
// before the flag write. Pairs with the consumer's ld.acquire.gpu.
__device__ __forceinline__ void strel(int* p, int v) {
    asm volatile("st.release.gpu.global.b32 [%0], %1;" :: "l"(p), "r"(v) : "memory");
}

// Fast tanh: MUFU.EX2 + MUFU.RCP path, rel err ~1e-6 (measured 3.1e-7 overall).
__device__ __forceinline__ float ftanh(float x) {
    float a = fabsf(x);
    float e = __expf(2.0f * a);
    float t = 1.0f - __fdividef(2.0f, e + 1.0f);
    return copysignf(t, x);
}

// ---------------------------------------------------------------------------
// Flag clear (graph replays re-run this before the pipe kernel).
// 64 CTAs x 256 threads x 4 = 65536 = BATCH*T_LEN.
// ---------------------------------------------------------------------------
__global__ void flag_clear_kernel() {
    int i = (blockIdx.x * 256 + threadIdx.x) * 4;
    #pragma unroll
    for (int k = 0; k < 4; k++) g_flag[i + k] = 0;
}

// ---------------------------------------------------------------------------
// Kernel 1: xp[t][b][j] = x[b][t][:] . W_ih0[j][:] + b_ih0[j] + b_hh0[j]
// Register-tiled GEMM with packed f32x2 FMAs.
// ---------------------------------------------------------------------------
__global__ __launch_bounds__(256) void xp_gemm_kernel(
    const float* __restrict__ x, const float* __restrict__ Wih0,
    const float* __restrict__ bih0, const float* __restrict__ bhh0)
{
    __shared__ __align__(16) float xs[16][128];
    __shared__ __align__(16) float ws[16][128];

    const int tid = threadIdx.x;
    const int tm  = tid >> 4;
    const int tn  = tid & 15;
    const int rbase = blockIdx.x * 128;

    ull acc2[8][4];
    #pragma unroll
    for (int i = 0; i < 8; i++)
        #pragma unroll
        for (int jj = 0; jj < 4; jj++) acc2[i][jj] = 0ull;

    const int lrow = tid & 127;
    const int kg   = tid >> 7;

    const float* gx = x    + (size_t)(rbase + lrow) * DIN + kg * 8;
    const float* gw = Wih0 + (size_t)lrow * DIN + kg * 8;

    for (int k0 = 0; k0 < DIN; k0 += 16) {
        float4 xa = *(const float4*)(gx + k0);
        float4 xb = *(const float4*)(gx + k0 + 4);
        float4 wa = *(const float4*)(gw + k0);
        float4 wb = *(const float4*)(gw + k0 + 4);
        __syncthreads();
        xs[kg*8+0][lrow] = xa.x; xs[kg*8+1][lrow] = xa.y;
        xs[kg*8+2][lrow] = xa.z; xs[kg*8+3][lrow] = xa.w;
        xs[kg*8+4][lrow] = xb.x; xs[kg*8+5][lrow] = xb.y;
        xs[kg*8+6][lrow] = xb.z; xs[kg*8+7][lrow] = xb.w;
        ws[kg*8+0][lrow] = wa.x; ws[kg*8+1][lrow] = wa.y;
        ws[kg*8+2][lrow] = wa.z; ws[kg*8+3][lrow] = wa.w;
        ws[kg*8+4][lrow] = wb.x; ws[kg*8+5][lrow] = wb.y;
        ws[kg*8+6][lrow] = wb.z; ws[kg*8+7][lrow] = wb.w;
        __syncthreads();

        #pragma unroll
        for (int kk = 0; kk < 16; kk++) {
            float am[8];
            *(float4*)&am[0] = *(const float4*)&xs[kk][tm*8];
            *(float4*)&am[4] = *(const float4*)&xs[kk][tm*8+4];
            ull bn2[4];
            *(ulonglong2*)&bn2[0] = *(const ulonglong2*)&ws[kk][tn*8];
            *(ulonglong2*)&bn2[2] = *(const ulonglong2*)&ws[kk][tn*8+4];
            #pragma unroll
            for (int i = 0; i < 8; i++) {
                ull a2 = dup2(am[i]);
                #pragma unroll
                for (int jj = 0; jj < 4; jj++)
                    fma2(acc2[i][jj], a2, bn2[jj]);
            }
        }
    }

    float bias[8];
    #pragma unroll
    for (int jj = 0; jj < 8; jj++) bias[jj] = bih0[tn*8+jj] + bhh0[tn*8+jj];

    #pragma unroll
    for (int i = 0; i < 8; i++) {
        int r  = rbase + tm*8 + i;
        int bb = r >> 11;
        int tt = r & 2047;
        float* dst = g_xp + ((size_t)tt * BATCH + bb) * HID + tn*8;
        float c[8];
        #pragma unroll
        for (int jj = 0; jj < 4; jj++) unpack2(acc2[i][jj], c[2*jj], c[2*jj+1]);
        float4 v0 = make_float4(c[0]+bias[0], c[1]+bias[1],
                                c[2]+bias[2], c[3]+bias[3]);
        float4 v1 = make_float4(c[4]+bias[4], c[5]+bias[5],
                                c[6]+bias[6], c[7]+bias[7]);
        *(float4*)dst       = v0;
        *(float4*)(dst + 4) = v1;
    }
}

// ---------------------------------------------------------------------------
// Kernel 2: layer-pipelined RNN. 64 CTAs, all co-resident (grid < 148 SMs
// => wave-1 co-scheduling guaranteed; spin loops cannot deadlock).
//   CTA b      (b < 32): PRODUCER — layer-0 recurrence for batch b.
//       h0[t] = tanh(xp[t] + W_hh0 h0[t-1]); publish to g_h0 + release flag.
//   CTA 32+b           : CONSUMER — layer-1 recurrence for batch b.
//       h1[t] = tanh(bias1 + W_ih1 h0[t] + W_hh1 h1[t-1]); writes output.
//       Prefetches h0[t+2] (flag spin + LDG overlap the issue-bound compute).
// Thread map in both roles: j = tid>>1 (unit), half = tid&1 (k-range);
// pair reduction via shfl.bfly(1); one __syncthreads per step.
// Producer is faster per step than consumer, so its lead grows and the
// consumer's flag checks are nearly always pre-satisfied.
// ---------------------------------------------------------------------------
__global__ __launch_bounds__(256, 1) void rnn_pipe_kernel(
    const float* __restrict__ Whh0, const float* __restrict__ Wih1,
    const float* __restrict__ Whh1, const float* __restrict__ bih1,
    const float* __restrict__ bhh1, float* __restrict__ out)
{
    const int tid  = threadIdx.x;
    const int j    = tid >> 1;
    const int half = tid & 1;
    const int jsk  = j + ((j >> 6) << 2);          // skewed store index
    const int rb   = (half << 6) + (half << 2);    // skewed read base = half*68

    if (blockIdx.x < BATCH) {
        // ================= PRODUCER (layer 0) =================
        const int b = blockIdx.x;
        __shared__ __align__(16) float h0s[2][HPAD];

        ull w0[32];
        {
            const float* s0 = Whh0 + j * HID + half * 64;
            #pragma unroll
            for (int i = 0; i < 32; i++) w0[i] = *(const ull*)(s0 + 2*i);
        }

        if (tid < HPAD) h0s[0][tid] = 0.f;

        const float* xpb = g_xp + b * HID + j;
        float xp_c = xpb[0];
        float xp_n = xpb[(size_t)1 * BATCH * HID];
        __syncthreads();

        float* h0g = g_h0 + (size_t)b * T_LEN * HID;
        int*   flg = g_flag + b * T_LEN;

        for (int t = 0; t < T_LEN; t++) {
            const int cur = t & 1, nxt = cur ^ 1;

            int tp = t + 2; tp = tp < T_LEN - 1 ? tp : T_LEN - 1;
            float xp_f = __ldg(xpb + (size_t)tp * BATCH * HID);

            ull a0 = 0, a1 = 0, a2 = 0, a3 = 0;
            const ulonglong2* hv = (const ulonglong2*)&h0s[cur][rb];
            #pragma unroll
            for (int i = 0; i < 8; i++) {
                ulonglong2 p0 = hv[2*i];
                fma2(a0, w0[4*i+0], p0.x);
                fma2(a1, w0[4*i+1], p0.y);
                ulonglong2 p1 = hv[2*i+1];
                fma2(a2, w0[4*i+2], p1.x);
                fma2(a3, w0[4*i+3], p1.y);
            }
            float s = (sum2(a0) + sum2(a1)) + (sum2(a2) + sum2(a3));
            float o = __shfl_xor_sync(0xffffffffu, s, 1);
            float v = ftanh(xp_c + s + o);
            if (!half)
                h0s[nxt][jsk] = v;               // even lane: SMEM state
            else
                h0g[(size_t)t * HID + j] = v;    // odd lane: publish h0[t]
            __syncthreads();
            if (tid == 0)                         // release-store flag
                strel(flg + t, 1);
            xp_c = xp_n;
            xp_n = xp_f;
        }
    } else {
        // ================= CONSUMER (layer 1) =================
        const int b = blockIdx.x - BATCH;
        __shared__ __align__(16) float h0b[2][HPAD];
        __shared__ __align__(16) float h1s[2][HPAD];

        ull wa[32], wb[32];
        {
            const float* sa = Wih1 + j * HID + half * 64;
            const float* sb = Whh1 + j * HID + half * 64;
            #pragma unroll
            for (int i = 0; i < 32; i++) {
                wa[i] = *(const ull*)(sa + 2*i);
                wb[i] = *(const ull*)(sb + 2*i);
            }
        }
        const float bias1 = bih1[j] + bhh1[j];

        if (tid < HPAD) h1s[0][tid] = 0.f;

        const float* h0g = g_h0 + (size_t)b * T_LEN * HID;
        const int*   flg = g_flag + b * T_LEN;

        // Prologue: fetch h0[0] -> h0b[0], h0[1] -> h0b[1].
        if (tid < 64) {
            int tt = tid >> 5;          // 0 or 1
            int lt = tid & 31;
            while (ldacq(flg + tt) == 0) {}
            float4 d = *(const float4*)(h0g + (size_t)tt * HID + 4*lt);
            int jb = 4*lt; int sk = jb + ((jb >> 6) << 2);
            *(float4*)&h0b[tt][sk] = d;
        }
        __syncthreads();

        float* outb = out + (size_t)b * T_LEN * HID;

        for (int t = 0; t < T_LEN; t++) {
            const int cur = t & 1, nxt = cur ^ 1;

            // Prefetch h0[t+2] into regs (warp 0); STS after the end barrier.
            float4 pf;
            if (tid < 32) {
                int tf = t + 2; tf = tf < T_LEN ? tf : T_LEN - 1;
                while (ldacq(flg + tf) == 0) {}
                pf = *(const float4*)(h0g + (size_t)tf * HID + 4*tid);
            }

            // W_ih1[j] . h0[t] partial
            ull a0 = 0, a1 = 0, a2 = 0, a3 = 0;
            const ulonglong2* ha = (const ulonglong2*)&h0b[cur][rb];
            #pragma unroll
            for (int i = 0; i < 8; i++) {
                ulonglong2 p0 = ha[2*i];
                fma2(a0, wa[4*i+0], p0.x);
                fma2(a1, wa[4*i+1], p0.y);
                ulonglong2 p1 = ha[2*i+1];
                fma2(a2, wa[4*i+2], p1.x);
                fma2(a3, wa[4*i+3], p1.y);
            }
            // W_hh1[j] . h1[t-1] partial
            ull c0 = 0, c1 = 0, c2 = 0, c3 = 0;
            const ulonglong2* hc = (const ulonglong2*)&h1s[cur][rb];
            #pragma unroll
            for (int i = 0; i < 8; i++) {
                ulonglong2 p0 = hc[2*i];
                fma2(c0, wb[4*i+0], p0.x);
                fma2(c1, wb[4*i+1], p0.y);
                ulonglong2 p1 = hc[2*i+1];
                fma2(c2, wb[4*i+2], p1.x);
                fma2(c3, wb[4*i+3], p1.y);
            }
            float s = ((sum2(a0) + sum2(a1)) + (sum2(a2) + sum2(a3)))
                    + ((sum2(c0) + sum2(c1)) + (sum2(c2) + sum2(c3)));
            float o = __shfl_xor_sync(0xffffffffu, s, 1);
            float v = ftanh(bias1 + s + o);
            if (!half)
                h1s[nxt][jsk] = v;               // even lane: SMEM state
            else
                outb[(size_t)t * HID + j] = v;   // odd lane: output
            __syncthreads();

            // Write the prefetched h0[t+2] into the buffer just consumed;
            // its next read (step t+2) is separated by step t+1's barrier.
            if (tid < 32) {
                int jb = 4*tid; int sk = jb + ((jb >> 6) << 2);
                *(float4*)&h0b[cur][sk] = pf;
            }
        }
    }
}

extern "C" void kernel_launch(void* const* d_in, const int* in_sizes, int n_in,
                              void* d_out, int out_size)
{
    const float* x    = (const float*)d_in[0];
    const float* Wih0 = (const float*)d_in[1];
    const float* Whh0 = (const float*)d_in[2];
    const float* bih0 = (const float*)d_in[3];
    const float* bhh0 = (const float*)d_in[4];
    const float* Wih1 = (const float*)d_in[5];
    const float* Whh1 = (const float*)d_in[6];
    const float* bih1 = (const float*)d_in[7];
    const float* bhh1 = (const float*)d_in[8];
    float* out = (float*)d_out;

    flag_clear_kernel<<<64, 256>>>();
    xp_gemm_kernel<<<(T_LEN * BATCH) / 128, 256>>>(x, Wih0, bih0, bhh0);
    rnn_pipe_kernel<<<2 * BATCH, 256>>>(Whh0, Wih1, Whh1, bih1, bhh1, out);
}